// round 2
// baseline (speedup 1.0000x reference)
#include <cuda_runtime.h>
#include <math.h>

#define N_NODES 50000
#define N_EDGES 800000

// ---- scratch (device globals; no allocation allowed) ----
__device__ __align__(16) float g_h1[N_NODES * 256];
__device__ __align__(16) float g_h2[N_NODES * 256];
__device__ __align__(16) float g_z [N_NODES * 256];
__device__ float g_sim[N_EDGES];
__device__ float g_rnrm[N_NODES];
__device__ float g_irs[N_NODES];
__device__ float g_wself[N_NODES];
__device__ int   g_rowptr[N_NODES + 1];
__device__ int   g_wr[N_NODES];
__device__ int   g_cnt[N_NODES];
__device__ int   g_eid[N_EDGES];

// ================= CSR build (row/col fixed across the 3 layers) =============
__global__ void k_zero_cnt() {
    int i = blockIdx.x * blockDim.x + threadIdx.x;
    if (i < N_NODES) g_cnt[i] = 0;
}

__global__ void k_hist(const int* __restrict__ row) {
    for (int e = blockIdx.x * blockDim.x + threadIdx.x; e < N_EDGES;
         e += gridDim.x * blockDim.x)
        atomicAdd(&g_cnt[row[e]], 1);
}

// single-block exclusive scan over 50000 counts
__global__ void k_scan() {
    __shared__ int wsum[32];
    __shared__ int carry;
    int tid = threadIdx.x, lane = tid & 31, wid = tid >> 5;
    if (tid == 0) carry = 0;
    __syncthreads();
    for (int base = 0; base < N_NODES; base += 1024) {
        int i = base + tid;
        int v = (i < N_NODES) ? g_cnt[i] : 0;
        int inc = v;
#pragma unroll
        for (int o = 1; o < 32; o <<= 1) {
            int y = __shfl_up_sync(0xffffffffu, inc, o);
            if (lane >= o) inc += y;
        }
        if (lane == 31) wsum[wid] = inc;
        __syncthreads();
        if (wid == 0) {
            int w = wsum[lane];
#pragma unroll
            for (int o = 1; o < 32; o <<= 1) {
                int y = __shfl_up_sync(0xffffffffu, w, o);
                if (lane >= o) w += y;
            }
            wsum[lane] = w;
        }
        __syncthreads();
        int pre = (wid > 0) ? wsum[wid - 1] : 0;
        int excl = carry + pre + inc - v;
        if (i < N_NODES) { g_rowptr[i] = excl; g_wr[i] = excl; }
        int chunk_total = wsum[31];
        __syncthreads();
        if (tid == 0) carry += chunk_total;
        __syncthreads();
    }
    if (tid == 0) g_rowptr[N_NODES] = carry;
}

__global__ void k_scatter(const int* __restrict__ row) {
    for (int e = blockIdx.x * blockDim.x + threadIdx.x; e < N_EDGES;
         e += gridDim.x * blockDim.x) {
        int p = atomicAdd(&g_wr[row[e]], 1);
        g_eid[p] = e;
    }
}

// ================= per-layer kernels =========================================
// reciprocal node norms
template <int IN>
__global__ void k_norms(const float* __restrict__ x) {
    int n = (blockIdx.x * blockDim.x + threadIdx.x) >> 5;
    if (n >= N_NODES) return;
    int lane = threadIdx.x & 31;
    const float4* xr = (const float4*)(x + (size_t)n * IN);
    float s = 0.0f;
#pragma unroll
    for (int i = 0; i < IN / 128; i++) {
        float4 v = xr[lane + 32 * i];
        s += v.x * v.x + v.y * v.y + v.z * v.z + v.w * v.w;
    }
#pragma unroll
    for (int o = 16; o; o >>= 1) s += __shfl_xor_sync(0xffffffffu, s, o);
    if (lane == 0) g_rnrm[n] = 1.0f / fmaxf(sqrtf(s), 1e-12f);
}

// warp-per-edge SDDMM: thresholded cosine similarity
template <int IN>
__global__ void k_sim(const float* __restrict__ x, const int* __restrict__ row,
                      const int* __restrict__ col) {
    int e = (blockIdx.x * blockDim.x + threadIdx.x) >> 5;
    if (e >= N_EDGES) return;
    int lane = threadIdx.x & 31;
    int r = row[e], c = col[e];
    const float4* xa = (const float4*)(x + (size_t)r * IN);
    const float4* xb = (const float4*)(x + (size_t)c * IN);
    float s = 0.0f;
#pragma unroll
    for (int i = 0; i < IN / 128; i++) {
        float4 a = xa[lane + 32 * i];
        float4 b = xb[lane + 32 * i];
        s += a.x * b.x + a.y * b.y + a.z * b.z + a.w * b.w;
    }
#pragma unroll
    for (int o = 16; o; o >>= 1) s += __shfl_xor_sync(0xffffffffu, s, o);
    if (lane == 0) {
        float sim = s * g_rnrm[r] * g_rnrm[c];
        g_sim[e] = (sim < 0.1f) ? 0.0f : sim;
    }
}

// per-node rowsum + degree (CSR, no atomics)
__global__ void k_rowdeg() {
    int n = (blockIdx.x * blockDim.x + threadIdx.x) >> 5;
    if (n >= N_NODES) return;
    int lane = threadIdx.x & 31;
    int b = g_rowptr[n], e2 = g_rowptr[n + 1];
    float s = 0.0f;
    int cnt = 0;
    for (int j = b + lane; j < e2; j += 32) {
        float v = g_sim[g_eid[j]];
        s += v;
        cnt += (v != 0.0f);
    }
#pragma unroll
    for (int o = 16; o; o >>= 1) {
        s += __shfl_xor_sync(0xffffffffu, s, o);
        cnt += __shfl_xor_sync(0xffffffffu, cnt, o);
    }
    if (lane == 0) {
        g_irs[n] = (s > 0.0f) ? (1.0f / s) : 0.0f;
        g_wself[n] = expf(1.0f / (float)(cnt + 1));
    }
}

// ====== tiled SGEMM: Z[n, f] = sum_d X[n,d] * W[h, d, o], f = h*OPH + o ======
// BM=64, BK=16. TN=4 -> BN=64 (layers 0/1), TN=1 -> BN=16 (layer 2).
template <int IN, int OPH, int BN, int TN>
__global__ void __launch_bounds__(256) k_gemm(const float* __restrict__ X,
                                              const float* __restrict__ W,
                                              float* __restrict__ Z,
                                              int OUTF) {
    constexpr int BM = 64, BK = 16;
    constexpr int TX = BN / TN;      // threads along cols
    constexpr int TY = 256 / TX;     // threads along rows (TY*4 == BM)
    __shared__ float sXT[BK][BM + 4];
    __shared__ float sW[BK][BN + 4];
    int tid = threadIdx.x;
    int tx = tid % TX, ty = tid / TX;
    int n0 = blockIdx.x * BM;
    int f0 = blockIdx.y * BN;
    int h = f0 / OPH;
    int o0 = f0 - h * OPH;
    float acc[4][TN];
#pragma unroll
    for (int i = 0; i < 4; i++)
#pragma unroll
        for (int j = 0; j < TN; j++) acc[i][j] = 0.0f;

    for (int k0 = 0; k0 < IN; k0 += BK) {
        // X tile: 64 rows x 16 d, transposed into sXT
        {
            int r = tid >> 2, c4 = (tid & 3) * 4;
            int n = n0 + r;
            float4 v = (n < N_NODES)
                           ? *(const float4*)&X[(size_t)n * IN + k0 + c4]
                           : make_float4(0.f, 0.f, 0.f, 0.f);
            sXT[c4 + 0][r] = v.x;
            sXT[c4 + 1][r] = v.y;
            sXT[c4 + 2][r] = v.z;
            sXT[c4 + 3][r] = v.w;
        }
        // W tile: BK x BN
        {
            constexpr int ROWV = BN / 4;   // float4 per k-row
            for (int idx = tid; idx < BK * ROWV; idx += 256) {
                int kk = idx / ROWV, f4 = (idx % ROWV) * 4;
                float4 w = *(const float4*)&W[((size_t)h * IN + k0 + kk) * OPH + o0 + f4];
                *(float4*)&sW[kk][f4] = w;
            }
        }
        __syncthreads();
#pragma unroll
        for (int k = 0; k < BK; k++) {
            float4 a = *(const float4*)&sXT[k][ty * 4];
            float av[4] = {a.x, a.y, a.z, a.w};
            float bv[TN];
            if (TN == 4) {
                float4 b = *(const float4*)&sW[k][tx * 4];
                bv[0] = b.x; bv[1] = b.y; bv[2] = b.z; bv[3] = b.w;
            } else {
                bv[0] = sW[k][tx];
            }
#pragma unroll
            for (int i = 0; i < 4; i++)
#pragma unroll
                for (int j = 0; j < TN; j++) acc[i][j] += av[i] * bv[j];
        }
        __syncthreads();
    }
#pragma unroll
    for (int i = 0; i < 4; i++) {
        int n = n0 + ty * 4 + i;
        if (n < N_NODES) {
            if (TN == 4) {
                float4 v = make_float4(acc[i][0], acc[i][1], acc[i][2], acc[i][3]);
                *(float4*)&Z[(size_t)n * OUTF + f0 + tx * 4] = v;
            } else {
                Z[(size_t)n * OUTF + f0 + tx] = acc[i][0];
            }
        }
    }
}

// warp-per-node aggregation: out[n] = w_self*z[n] + sum_e exp(att_e)*z[col_e]
template <int OUTF, bool RELU>
__global__ void k_agg(const float* __restrict__ z, const int* __restrict__ col,
                      float* __restrict__ out) {
    int n = (blockIdx.x * blockDim.x + threadIdx.x) >> 5;
    if (n >= N_NODES) return;
    int lane = threadIdx.x & 31;
    constexpr int FPL = OUTF / 32 ? OUTF / 32 : 1;   // 8 for 256, 1 for 16 (lane<16)
    float ws = g_wself[n], irs = g_irs[n];
    float acc[FPL];
#pragma unroll
    for (int i = 0; i < FPL; i++) {
        int f = lane + 32 * i;
        acc[i] = (f < OUTF) ? ws * z[(size_t)n * OUTF + f] : 0.0f;
    }
    int b = g_rowptr[n], e2 = g_rowptr[n + 1];
    for (int j = b; j < e2; j++) {
        int e = g_eid[j];
        float s = g_sim[e];
        if (s != 0.0f) {
            float w = expf(s * irs);
            int c = col[e];
#pragma unroll
            for (int i = 0; i < FPL; i++) {
                int f = lane + 32 * i;
                if (f < OUTF) acc[i] += w * z[(size_t)c * OUTF + f];
            }
        }
    }
#pragma unroll
    for (int i = 0; i < FPL; i++) {
        int f = lane + 32 * i;
        if (f < OUTF) {
            float v = acc[i];
            if (RELU) v = (v >= 0.0f) ? v : 0.01f * v;
            out[(size_t)n * OUTF + f] = v;
        }
    }
}

// ================= driver ====================================================
extern "C" void kernel_launch(void* const* d_in, const int* in_sizes, int n_in,
                              void* d_out, int out_size) {
    const float* x  = (const float*)d_in[0];
    const float* W0 = (const float*)d_in[1];   // [4,128,64]
    const float* W1 = (const float*)d_in[2];   // [4,256,64]
    const float* W2 = (const float*)d_in[3];   // [1,256,16]
    const int*   row = (const int*)d_in[4];
    const int*   col = (const int*)d_in[5];
    float* out = (float*)d_out;

    float *h1, *h2, *z;
    cudaGetSymbolAddress((void**)&h1, g_h1);
    cudaGetSymbolAddress((void**)&h2, g_h2);
    cudaGetSymbolAddress((void**)&z,  g_z);

    const int NODE_WARP_BLOCKS = (N_NODES * 32 + 255) / 256;   // 6250
    const int EDGE_WARP_BLOCKS = (N_EDGES * 32 + 255) / 256;   // 100000
    const int GEMM_MB = (N_NODES + 63) / 64;                   // 782

    // ---- CSR (shared by all three layers) ----
    k_zero_cnt<<<(N_NODES + 255) / 256, 256>>>();
    k_hist<<<400, 256>>>(row);
    k_scan<<<1, 1024>>>();
    k_scatter<<<400, 256>>>(row);

    // ---- layer 0: x[50000,128] -> h1[50000,256], relu ----
    k_norms<128><<<NODE_WARP_BLOCKS, 256>>>(x);
    k_sim<128><<<EDGE_WARP_BLOCKS, 256>>>(x, row, col);
    k_rowdeg<<<NODE_WARP_BLOCKS, 256>>>();
    k_gemm<128, 64, 64, 4><<<dim3(GEMM_MB, 4), 256>>>(x, W0, z, 256);
    k_agg<256, true><<<NODE_WARP_BLOCKS, 256>>>(z, col, h1);

    // ---- layer 1: h1[50000,256] -> h2[50000,256], relu ----
    k_norms<256><<<NODE_WARP_BLOCKS, 256>>>(h1);
    k_sim<256><<<EDGE_WARP_BLOCKS, 256>>>(h1, row, col);
    k_rowdeg<<<NODE_WARP_BLOCKS, 256>>>();
    k_gemm<256, 64, 64, 4><<<dim3(GEMM_MB, 4), 256>>>(h1, W1, z, 256);
    k_agg<256, true><<<NODE_WARP_BLOCKS, 256>>>(z, col, h2);

    // ---- layer 2: h2[50000,256] -> out[50000,16], no act ----
    k_norms<256><<<NODE_WARP_BLOCKS, 256>>>(h2);
    k_sim<256><<<EDGE_WARP_BLOCKS, 256>>>(h2, row, col);
    k_rowdeg<<<NODE_WARP_BLOCKS, 256>>>();
    k_gemm<256, 16, 16, 1><<<dim3(GEMM_MB, 1), 256>>>(h2, W2, z, 16);
    k_agg<16, false><<<NODE_WARP_BLOCKS, 256>>>(z, col, out);
}